// round 11
// baseline (speedup 1.0000x reference)
#include <cuda_runtime.h>

#define N_ATOMS  1024
#define NSLOTS   512            // 2-atom slots per batch
#define TPB      256
#define NSEG     4              // k-segments of 64 slot-steps (k = 1..256)
#define KSTEPS   64
#define TOTSLOTS 772            // 512 + dup tail (max slot touched = 771)
#define ZR_OFF   (TOTSLOTS * 16)   // byte offset of ZR array after XY array

__device__ float g_partials[512];
__device__ unsigned int g_count = 0;

typedef unsigned long long u64;

__device__ __forceinline__ u64 fma2(u64 a, u64 b, u64 c) {
    u64 d; asm("fma.rn.f32x2 %0, %1, %2, %3;" : "=l"(d) : "l"(a), "l"(b), "l"(c)); return d;
}
__device__ __forceinline__ u64 add2(u64 a, u64 b) {
    u64 d; asm("add.rn.f32x2 %0, %1, %2;" : "=l"(d) : "l"(a), "l"(b)); return d;
}
__device__ __forceinline__ u64 mul2(u64 a, u64 b) {
    u64 d; asm("mul.rn.f32x2 %0, %1, %2;" : "=l"(d) : "l"(a), "l"(b)); return d;
}
__device__ __forceinline__ u64 pack2(float lo, float hi) {
    u64 d; asm("mov.b64 %0, {%1, %2};" : "=l"(d) : "f"(lo), "f"(hi)); return d;
}
__device__ __forceinline__ float fsqrt_approx(float x) {
    float r; asm("sqrt.approx.f32 %0, %1;" : "=f"(r) : "f"(x)); return r;
}

// load slot at byte offset 'off' within XY array; ZR line at +ZR_OFF (immediate)
#define LOAD_SLOT(s, off) do {                                               \
    ulonglong2 _q1 = *(const ulonglong2*)(smem_c + (off));                   \
    ulonglong2 _q2 = *(const ulonglong2*)(smem_c + (off) + ZR_OFF);          \
    s##x = _q1.x; s##y = _q1.y; s##z = _q2.x; s##r = _q2.y;                  \
} while (0)

// 2 pairs: packed dot-chain, scalar sqrt+max tail (fmaxf is the NaN guard), packed acc
#define PAIR2(X, Y, Z, R, s, ACC) do {                                       \
    u64 _d2 = add2(fma2(X, s##x, fma2(Y, s##y, fma2(Z, s##z, s##r))), R);    \
    float _a, _b;                                                            \
    asm("mov.b64 {%0, %1}, %2;" : "=f"(_a), "=f"(_b) : "l"(_d2));            \
    float _v0 = fmaxf(2.9f - fsqrt_approx(_a), 0.0f);                        \
    float _v1 = fmaxf(2.9f - fsqrt_approx(_b), 0.0f);                        \
    u64 _V = pack2(_v0, _v1);                                                \
    ACC = fma2(_V, _V, ACC);                                                 \
} while (0)

// one slot-step: both rows vs buffer P (4 atom pairs), then refill P (1 IADD)
#define STEP(P) do {                                                         \
    PAIR2(X0, Y0, Z0, R0, P, acc0);                                          \
    PAIR2(X1, Y1, Z1, R1, P, acc1);                                          \
    LOAD_SLOT(P, off);                                                       \
    off += 16;                                                               \
} while (0)

__global__ void __launch_bounds__(TPB, 4)
collapse_kernel(const float* __restrict__ coords,
                float* __restrict__ out,
                int nblocks, float inv_b)
{
    // [0, ZR_OFF): XY lines (x0,x1,y0,y1); [ZR_OFF, 2*ZR_OFF): ZR lines (z0,z1,r0,r1)
    __shared__ float4 slab[2 * TOTSLOTS];       // 24.7 KB
    __shared__ float  wsum[TPB / 32];
    __shared__ bool   isLast;
    const char* smem_c = (const char*)slab;

    const int t    = threadIdx.x;
    const int bx   = blockIdx.x;                // 0..7
    const int half = bx & 1;
    const int kseg = bx >> 1;                   // 0..3
    const int b    = blockIdx.y;

    // ---- prologue: thread t loads atoms 4t..4t+3, builds slots 2t, 2t+1 ----
    {
        const float4* cb4 = (const float4*)(coords + (size_t)b * (3 * N_ATOMS));
        float4 f0 = cb4[3 * t + 0];
        float4 f1 = cb4[3 * t + 1];
        float4 f2 = cb4[3 * t + 2];
        float x0 = f0.x, y0 = f0.y, z0 = f0.z;
        float x1 = f0.w, y1 = f1.x, z1 = f1.y;
        float x2 = f1.z, y2 = f1.w, z2 = f2.x;
        float x3 = f2.y, y3 = f2.z, z3 = f2.w;
        // bake eps/2 into r so d2 = ri + rj - 2 dot carries the reference's +1e-8
        float r0 = fmaf(x0, x0, fmaf(y0, y0, z0 * z0)) + 5e-9f;
        float r1 = fmaf(x1, x1, fmaf(y1, y1, z1 * z1)) + 5e-9f;
        float r2 = fmaf(x2, x2, fmaf(y2, y2, z2 * z2)) + 5e-9f;
        float r3 = fmaf(x3, x3, fmaf(y3, y3, z3 * z3)) + 5e-9f;
        float4 xyA = make_float4(x0, x1, y0, y1);
        float4 zrA = make_float4(z0, z1, r0, r1);
        float4 xyB = make_float4(x2, x3, y2, y3);
        float4 zrB = make_float4(z2, z3, r2, r3);
        slab[2 * t]                 = xyA;     // XY line of slot 2t
        slab[2 * t + 1]             = xyB;     // XY line of slot 2t+1
        slab[TOTSLOTS + 2 * t]      = zrA;     // ZR line of slot 2t
        slab[TOTSLOTS + 2 * t + 1]  = zrB;
        if (t < 130) {                          // dup tail: slots 512..771 mirror 0..259
            slab[NSLOTS + 2 * t]                = xyA;
            slab[NSLOTS + 2 * t + 1]            = xyB;
            slab[TOTSLOTS + NSLOTS + 2 * t]     = zrA;
            slab[TOTSLOTS + NSLOTS + 2 * t + 1] = zrB;
        }
    }
    __syncthreads();

    // ---- this thread owns slot ci = 256*half + t (atoms 2ci, 2ci+1) ----
    const int ci = 256 * half + t;

    // ---- row constants from own slot ----
    u64 X0,Y0,Z0,R0, X1,Y1,Z1,R1;
    float sx0, sx1, sy0, sy1, sz0, sz1, sr0, sr1;
    {
        float4 q1 = slab[ci];
        float4 q2 = slab[TOTSLOTS + ci];
        sx0 = q1.x; sx1 = q1.y; sy0 = q1.z; sy1 = q1.w;
        sz0 = q2.x; sz1 = q2.y; sr0 = q2.z; sr1 = q2.w;
        X0 = pack2(-2.f * sx0, -2.f * sx0);
        Y0 = pack2(-2.f * sy0, -2.f * sy0);
        Z0 = pack2(-2.f * sz0, -2.f * sz0);
        R0 = pack2(sr0, sr0);
        X1 = pack2(-2.f * sx1, -2.f * sx1);
        Y1 = pack2(-2.f * sy1, -2.f * sy1);
        Z1 = pack2(-2.f * sz1, -2.f * sz1);
        R1 = pack2(sr1, sr1);
    }

    // ---- prime 2-slot window at c0 = ci + 1 + 64*kseg (regs fit under cap) ----
    const int c0 = ci + 1 + KSTEPS * kseg;
    u64 Ax,Ay,Az,Ar, Bx,By,Bz,Br;
    LOAD_SLOT(A, 16 * c0);
    LOAD_SLOT(B, 16 * (c0 + 1));
    int off = 16 * (c0 + 2);

    u64 acc0 = 0, acc1 = 0;

    // ---- main loop: 64 slot-steps, 2-slot ping-pong ----
    #pragma unroll 4
    for (int it = 0; it < KSTEPS / 2; ++it) {
        STEP(A);
        STEP(B);
    }

    // ---- kseg3: slot-distance 256 counted by both partners -> subtract 0.5x ----
    if (kseg == NSEG - 1) {
        u64 Ex,Ey,Ez,Er;
        LOAD_SLOT(E, 16 * (ci + 256));
        const u64 NEGH = pack2(-0.5f, -0.5f);
        {
            u64 d2 = add2(fma2(X0, Ex, fma2(Y0, Ey, fma2(Z0, Ez, Er))), R0);
            float a, bb;
            asm("mov.b64 {%0, %1}, %2;" : "=f"(a), "=f"(bb) : "l"(d2));
            u64 V = pack2(fmaxf(2.9f - fsqrt_approx(a), 0.0f),
                          fmaxf(2.9f - fsqrt_approx(bb), 0.0f));
            acc0 = fma2(mul2(V, NEGH), V, acc0);
        }
        {
            u64 d2 = add2(fma2(X1, Ex, fma2(Y1, Ey, fma2(Z1, Ez, Er))), R1);
            float a, bb;
            asm("mov.b64 {%0, %1}, %2;" : "=f"(a), "=f"(bb) : "l"(d2));
            u64 V = pack2(fmaxf(2.9f - fsqrt_approx(a), 0.0f),
                          fmaxf(2.9f - fsqrt_approx(bb), 0.0f));
            acc1 = fma2(mul2(V, NEGH), V, acc1);
        }
    }

    // ---- unpack accumulators ----
    float a0f, a1f, a2f, a3f;
    asm("mov.b64 {%0, %1}, %2;" : "=f"(a0f), "=f"(a1f) : "l"(acc0));
    asm("mov.b64 {%0, %1}, %2;" : "=f"(a2f), "=f"(a3f) : "l"(acc1));
    float acc = (a0f + a1f) + (a2f + a3f);

    // ---- kseg0: intra-slot diagonal pair (2ci, 2ci+1) ----
    if (kseg == 0) {
        float dot = fmaf(sx0, sx1, fmaf(sy0, sy1, sz0 * sz1));
        float d2  = fmaf(-2.f, dot, sr0 + sr1);
        float v   = fmaxf(2.9f - fsqrt_approx(d2), 0.0f);
        acc = fmaf(v, v, acc);
    }

    // ---- intra-CTA reduction ----
    const int lane = t & 31, w = t >> 5;
    #pragma unroll
    for (int o = 16; o > 0; o >>= 1)
        acc += __shfl_down_sync(0xFFFFFFFFu, acc, o);
    if (lane == 0) wsum[w] = acc;
    __syncthreads();

    if (t == 0) {
        float s = 0.f;
        #pragma unroll
        for (int q = 0; q < TPB / 32; ++q) s += wsum[q];
        g_partials[blockIdx.y * gridDim.x + blockIdx.x] = s;
        __threadfence();
        unsigned int c = atomicAdd(&g_count, 1u);
        isLast = (c == (unsigned int)(nblocks - 1));
    }
    __syncthreads();

    // ---- last CTA: fixed-order deterministic final reduce ----
    if (isLast) {
        __threadfence();
        if (t < 32) {
            float s = 0.f;
            for (int k = t; k < nblocks; k += 32)
                s += g_partials[k];
            #pragma unroll
            for (int o = 16; o > 0; o >>= 1)
                s += __shfl_down_sync(0xFFFFFFFFu, s, o);
            if (t == 0) {
                out[0] = s * inv_b;
                g_count = 0;   // reset for graph replay
            }
        }
    }
}

extern "C" void kernel_launch(void* const* d_in, const int* in_sizes, int n_in,
                              void* d_out, int out_size)
{
    const float* coords = (const float*)d_in[0];
    const int B = in_sizes[0] / (3 * N_ATOMS);   // 64

    static bool configured = false;
    if (!configured) {
        cudaFuncSetAttribute(collapse_kernel,
                             cudaFuncAttributePreferredSharedMemoryCarveout, 100);
        configured = true;
    }

    dim3 grid(2 * NSEG, B);                      // (8, 64) = 512 CTAs, single wave
    const int nblocks = 2 * NSEG * B;
    collapse_kernel<<<grid, TPB>>>(coords, (float*)d_out, nblocks, 1.0f / (float)B);
}

// round 12
// speedup vs baseline: 1.0015x; 1.0015x over previous
#include <cuda_runtime.h>

#define N_ATOMS  1024
#define NSLOTS   512            // 2-atom slots per batch
#define TPB      256
#define NSEG     8              // k-segments of 32 slot-steps (k = 1..256)
#define KSTEPS   32
#define TOTSLOTS 772            // 512 + dup tail (max slot touched = 771)
#define ZR_OFF   (TOTSLOTS * 16)   // byte offset of ZR array after XY array

__device__ float g_partials[1024];
__device__ unsigned int g_count = 0;

typedef unsigned long long u64;

__device__ __forceinline__ u64 fma2(u64 a, u64 b, u64 c) {
    u64 d; asm("fma.rn.f32x2 %0, %1, %2, %3;" : "=l"(d) : "l"(a), "l"(b), "l"(c)); return d;
}
__device__ __forceinline__ u64 add2(u64 a, u64 b) {
    u64 d; asm("add.rn.f32x2 %0, %1, %2;" : "=l"(d) : "l"(a), "l"(b)); return d;
}
__device__ __forceinline__ u64 mul2(u64 a, u64 b) {
    u64 d; asm("mul.rn.f32x2 %0, %1, %2;" : "=l"(d) : "l"(a), "l"(b)); return d;
}
__device__ __forceinline__ u64 pack2(float lo, float hi) {
    u64 d; asm("mov.b64 %0, {%1, %2};" : "=l"(d) : "f"(lo), "f"(hi)); return d;
}
__device__ __forceinline__ float fsqrt_approx(float x) {
    float r; asm("sqrt.approx.f32 %0, %1;" : "=f"(r) : "f"(x)); return r;
}

// load slot at byte offset 'off' within XY array; ZR line at +ZR_OFF (immediate)
#define LOAD_SLOT(s, off) do {                                               \
    ulonglong2 _q1 = *(const ulonglong2*)(smem_c + (off));                   \
    ulonglong2 _q2 = *(const ulonglong2*)(smem_c + (off) + ZR_OFF);          \
    s##x = _q1.x; s##y = _q1.y; s##z = _q2.x; s##r = _q2.y;                  \
} while (0)

// 2 pairs: packed dot-chain, scalar sqrt+max tail (fmaxf is the NaN guard), packed acc
#define PAIR2(X, Y, Z, R, s, ACC) do {                                       \
    u64 _d2 = add2(fma2(X, s##x, fma2(Y, s##y, fma2(Z, s##z, s##r))), R);    \
    float _a, _b;                                                            \
    asm("mov.b64 {%0, %1}, %2;" : "=f"(_a), "=f"(_b) : "l"(_d2));            \
    float _v0 = fmaxf(2.9f - fsqrt_approx(_a), 0.0f);                        \
    float _v1 = fmaxf(2.9f - fsqrt_approx(_b), 0.0f);                        \
    u64 _V = pack2(_v0, _v1);                                                \
    ACC = fma2(_V, _V, ACC);                                                 \
} while (0)

// one slot-step: both rows vs buffer P (4 atom pairs), then refill P (1 IADD)
#define STEP(P) do {                                                         \
    PAIR2(X0, Y0, Z0, R0, P, acc0);                                          \
    PAIR2(X1, Y1, Z1, R1, P, acc1);                                          \
    LOAD_SLOT(P, off);                                                       \
    off += 16;                                                               \
} while (0)

__global__ void __launch_bounds__(TPB, 4)
collapse_kernel(const float* __restrict__ coords,
                float* __restrict__ out,
                int nblocks, float inv_b)
{
    // [0, ZR_OFF): XY lines (x0,x1,y0,y1); [ZR_OFF, 2*ZR_OFF): ZR lines (z0,z1,r0,r1)
    __shared__ float4 slab[2 * TOTSLOTS];       // 24.7 KB
    __shared__ float  wsum[TPB / 32];
    __shared__ bool   isLast;
    const char* smem_c = (const char*)slab;

    const int t    = threadIdx.x;
    const int bx   = blockIdx.x;                // 0..15
    const int half = bx & 1;
    const int kseg = bx >> 1;                   // 0..7
    const int b    = blockIdx.y;

    // ---- prologue: thread t loads atoms 4t..4t+3, builds slots 2t, 2t+1 ----
    {
        const float4* cb4 = (const float4*)(coords + (size_t)b * (3 * N_ATOMS));
        float4 f0 = cb4[3 * t + 0];
        float4 f1 = cb4[3 * t + 1];
        float4 f2 = cb4[3 * t + 2];
        float x0 = f0.x, y0 = f0.y, z0 = f0.z;
        float x1 = f0.w, y1 = f1.x, z1 = f1.y;
        float x2 = f1.z, y2 = f1.w, z2 = f2.x;
        float x3 = f2.y, y3 = f2.z, z3 = f2.w;
        // bake eps/2 into r so d2 = ri + rj - 2 dot carries the reference's +1e-8
        float r0 = fmaf(x0, x0, fmaf(y0, y0, z0 * z0)) + 5e-9f;
        float r1 = fmaf(x1, x1, fmaf(y1, y1, z1 * z1)) + 5e-9f;
        float r2 = fmaf(x2, x2, fmaf(y2, y2, z2 * z2)) + 5e-9f;
        float r3 = fmaf(x3, x3, fmaf(y3, y3, z3 * z3)) + 5e-9f;
        float4 xyA = make_float4(x0, x1, y0, y1);
        float4 zrA = make_float4(z0, z1, r0, r1);
        float4 xyB = make_float4(x2, x3, y2, y3);
        float4 zrB = make_float4(z2, z3, r2, r3);
        slab[2 * t]                 = xyA;     // XY line of slot 2t
        slab[2 * t + 1]             = xyB;     // XY line of slot 2t+1
        slab[TOTSLOTS + 2 * t]      = zrA;     // ZR line of slot 2t
        slab[TOTSLOTS + 2 * t + 1]  = zrB;
        if (t < 130) {                          // dup tail: slots 512..771 mirror 0..259
            slab[NSLOTS + 2 * t]                = xyA;
            slab[NSLOTS + 2 * t + 1]            = xyB;
            slab[TOTSLOTS + NSLOTS + 2 * t]     = zrA;
            slab[TOTSLOTS + NSLOTS + 2 * t + 1] = zrB;
        }
    }
    __syncthreads();

    // ---- this thread owns slot ci = 256*half + t (atoms 2ci, 2ci+1) ----
    const int ci = 256 * half + t;

    // ---- row constants from own slot ----
    u64 X0,Y0,Z0,R0, X1,Y1,Z1,R1;
    float sx0, sx1, sy0, sy1, sz0, sz1, sr0, sr1;
    {
        float4 q1 = slab[ci];
        float4 q2 = slab[TOTSLOTS + ci];
        sx0 = q1.x; sx1 = q1.y; sy0 = q1.z; sy1 = q1.w;
        sz0 = q2.x; sz1 = q2.y; sr0 = q2.z; sr1 = q2.w;
        X0 = pack2(-2.f * sx0, -2.f * sx0);
        Y0 = pack2(-2.f * sy0, -2.f * sy0);
        Z0 = pack2(-2.f * sz0, -2.f * sz0);
        R0 = pack2(sr0, sr0);
        X1 = pack2(-2.f * sx1, -2.f * sx1);
        Y1 = pack2(-2.f * sy1, -2.f * sy1);
        Z1 = pack2(-2.f * sz1, -2.f * sz1);
        R1 = pack2(sr1, sr1);
    }

    // ---- prime 2-slot window at c0 = ci + 1 + 32*kseg ----
    const int c0 = ci + 1 + KSTEPS * kseg;
    u64 Ax,Ay,Az,Ar, Bx,By,Bz,Br;
    LOAD_SLOT(A, 16 * c0);
    LOAD_SLOT(B, 16 * (c0 + 1));
    int off = 16 * (c0 + 2);

    u64 acc0 = 0, acc1 = 0;

    // ---- main loop: 32 slot-steps, 2-slot ping-pong ----
    #pragma unroll 4
    for (int it = 0; it < KSTEPS / 2; ++it) {
        STEP(A);
        STEP(B);
    }

    // ---- last kseg: slot-distance 256 counted by both partners -> subtract 0.5x ----
    if (kseg == NSEG - 1) {
        u64 Ex,Ey,Ez,Er;
        LOAD_SLOT(E, 16 * (ci + 256));
        const u64 NEGH = pack2(-0.5f, -0.5f);
        {
            u64 d2 = add2(fma2(X0, Ex, fma2(Y0, Ey, fma2(Z0, Ez, Er))), R0);
            float a, bb;
            asm("mov.b64 {%0, %1}, %2;" : "=f"(a), "=f"(bb) : "l"(d2));
            u64 V = pack2(fmaxf(2.9f - fsqrt_approx(a), 0.0f),
                          fmaxf(2.9f - fsqrt_approx(bb), 0.0f));
            acc0 = fma2(mul2(V, NEGH), V, acc0);
        }
        {
            u64 d2 = add2(fma2(X1, Ex, fma2(Y1, Ey, fma2(Z1, Ez, Er))), R1);
            float a, bb;
            asm("mov.b64 {%0, %1}, %2;" : "=f"(a), "=f"(bb) : "l"(d2));
            u64 V = pack2(fmaxf(2.9f - fsqrt_approx(a), 0.0f),
                          fmaxf(2.9f - fsqrt_approx(bb), 0.0f));
            acc1 = fma2(mul2(V, NEGH), V, acc1);
        }
    }

    // ---- unpack accumulators ----
    float a0f, a1f, a2f, a3f;
    asm("mov.b64 {%0, %1}, %2;" : "=f"(a0f), "=f"(a1f) : "l"(acc0));
    asm("mov.b64 {%0, %1}, %2;" : "=f"(a2f), "=f"(a3f) : "l"(acc1));
    float acc = (a0f + a1f) + (a2f + a3f);

    // ---- kseg0: intra-slot diagonal pair (2ci, 2ci+1) ----
    if (kseg == 0) {
        float dot = fmaf(sx0, sx1, fmaf(sy0, sy1, sz0 * sz1));
        float d2  = fmaf(-2.f, dot, sr0 + sr1);
        float v   = fmaxf(2.9f - fsqrt_approx(d2), 0.0f);
        acc = fmaf(v, v, acc);
    }

    // ---- intra-CTA reduction ----
    const int lane = t & 31, w = t >> 5;
    #pragma unroll
    for (int o = 16; o > 0; o >>= 1)
        acc += __shfl_down_sync(0xFFFFFFFFu, acc, o);
    if (lane == 0) wsum[w] = acc;
    __syncthreads();

    if (t == 0) {
        float s = 0.f;
        #pragma unroll
        for (int q = 0; q < TPB / 32; ++q) s += wsum[q];
        g_partials[blockIdx.y * gridDim.x + blockIdx.x] = s;
        __threadfence();
        unsigned int c = atomicAdd(&g_count, 1u);
        isLast = (c == (unsigned int)(nblocks - 1));
    }
    __syncthreads();

    // ---- last CTA: fixed-order deterministic final reduce ----
    if (isLast) {
        __threadfence();
        if (t < 32) {
            float s = 0.f;
            for (int k = t; k < nblocks; k += 32)
                s += g_partials[k];
            #pragma unroll
            for (int o = 16; o > 0; o >>= 1)
                s += __shfl_down_sync(0xFFFFFFFFu, s, o);
            if (t == 0) {
                out[0] = s * inv_b;
                g_count = 0;   // reset for graph replay
            }
        }
    }
}

extern "C" void kernel_launch(void* const* d_in, const int* in_sizes, int n_in,
                              void* d_out, int out_size)
{
    const float* coords = (const float*)d_in[0];
    const int B = in_sizes[0] / (3 * N_ATOMS);   // 64

    static bool configured = false;
    if (!configured) {
        cudaFuncSetAttribute(collapse_kernel,
                             cudaFuncAttributePreferredSharedMemoryCarveout, 100);
        configured = true;
    }

    dim3 grid(2 * NSEG, B);                      // (16, 64) = 1024 CTAs
    const int nblocks = 2 * NSEG * B;
    collapse_kernel<<<grid, TPB>>>(coords, (float*)d_out, nblocks, 1.0f / (float)B);
}